// round 1
// baseline (speedup 1.0000x reference)
#include <cuda_runtime.h>
#include <cuda_bf16.h>
#include <math.h>
#include <math_constants.h>

#define Bn 16
#define Gn 32
#define Nn 8400
#define NCc 80
#define BINSc 16
#define CH 144          // 4*BINS + NC
#define EPSf 1e-9f

// ---------------- scratch (device globals; no runtime alloc) ----------------
__device__ float4 g_pred[Bn * Nn];                 // pred boxes (x1,y1,x2,y2)
__device__ float4 g_lse[Bn * Nn];                  // per-side logsumexp of dfl logits
__device__ float  g_align[(size_t)Bn * Gn * Nn];   // raw align metric
__device__ float  g_overlap[(size_t)Bn * Gn * Nn]; // raw IoU
__device__ unsigned char g_ingts[(size_t)Bn * Gn * Nn];
__device__ unsigned char g_mask[(size_t)Bn * Gn * Nn];
__device__ float  g_ovmax[Bn * Gn];
__device__ float  g_almax[Bn * Gn];
__device__ unsigned char g_fg[Bn * Nn];
__device__ int    g_matched[Bn * Nn];
__device__ double g_acc[3];                        // ciou, dfl, focal
__device__ int    g_cnt;

// ---------------- helpers ----------------
__device__ __forceinline__ void decode_anchor(int n, const float*& p,
    const float* p0, const float* p1, const float* p2,
    int& hw, int& W, int& HW, float& stride)
{
    if (n < 6400)      { p = p0; hw = n;        W = 80; HW = 6400; stride = 8.f;  }
    else if (n < 8000) { p = p1; hw = n - 6400; W = 40; HW = 1600; stride = 16.f; }
    else               { p = p2; hw = n - 8000; W = 20; HW = 400;  stride = 32.f; }
}

__device__ __forceinline__ double blkReduce(double v)
{
    __shared__ double sh[8];
    int lane = threadIdx.x & 31, w = threadIdx.x >> 5;
    #pragma unroll
    for (int o = 16; o; o >>= 1) v += __shfl_down_sync(0xffffffffu, v, o);
    if (lane == 0) sh[w] = v;
    __syncthreads();
    v = (threadIdx.x < 8) ? sh[threadIdx.x] : 0.0;
    if (w == 0) {
        #pragma unroll
        for (int o = 4; o; o >>= 1) v += __shfl_down_sync(0xffu, v, o);
    }
    __syncthreads();
    return v;
}

// ---------------- kernels ----------------
__global__ void k_init()
{
    if (threadIdx.x < 3) g_acc[threadIdx.x] = 0.0;
    if (threadIdx.x == 0) g_cnt = 0;
}

// per-anchor: DFL softmax -> dist -> pred box; store per-side logsumexp
__global__ void k_pred(const float* __restrict__ p0, const float* __restrict__ p1,
                       const float* __restrict__ p2)
{
    int t = blockIdx.x * blockDim.x + threadIdx.x;
    if (t >= Bn * Nn) return;
    int b = t / Nn, n = t % Nn;
    const float* p; int hw, W, HW; float stride;
    decode_anchor(n, p, p0, p1, p2, hw, W, HW, stride);
    const float* base = p + ((size_t)b * CH) * HW + hw;
    float cx = ((hw % W) + 0.5f) * stride;
    float cy = ((hw / W) + 0.5f) * stride;
    float dist[4], lse[4];
    #pragma unroll
    for (int s = 0; s < 4; s++) {
        float l[BINSc], m = -1e30f;
        #pragma unroll
        for (int j = 0; j < BINSc; j++) {
            l[j] = base[(size_t)(s * BINSc + j) * HW];
            m = fmaxf(m, l[j]);
        }
        float sum = 0.f, ws = 0.f;
        #pragma unroll
        for (int j = 0; j < BINSc; j++) {
            float e = expf(l[j] - m);
            sum += e; ws += (float)j * e;
        }
        dist[s] = ws / sum * stride;
        lse[s] = m + logf(sum);
    }
    g_pred[t] = make_float4(cx - dist[0], cy - dist[1], cx + dist[2], cy + dist[3]);
    g_lse[t]  = make_float4(lse[0], lse[1], lse[2], lse[3]);
}

// pairwise (b,g,n): raw IoU, raw align, in_gts, zero mask
__global__ void k_pair(const float* __restrict__ p0, const float* __restrict__ p1,
                       const float* __restrict__ p2,
                       const float* __restrict__ gtb, const int* __restrict__ gtl)
{
    int b = blockIdx.y;
    int n = blockIdx.x * blockDim.x + threadIdx.x;
    __shared__ float sgt[Gn][4];
    __shared__ int   slab[Gn];
    if (threadIdx.x < Gn) {
        int g = threadIdx.x;
        slab[g] = gtl[b * Gn + g];
        #pragma unroll
        for (int k = 0; k < 4; k++) sgt[g][k] = gtb[(b * Gn + g) * 4 + k];
    }
    __syncthreads();
    if (n >= Nn) return;
    const float* p; int hw, W, HW; float stride;
    decode_anchor(n, p, p0, p1, p2, hw, W, HW, stride);
    float4 pb = g_pred[b * Nn + n];
    float cx = ((hw % W) + 0.5f) * stride;
    float cy = ((hw / W) + 0.5f) * stride;
    float ap = fmaxf(pb.z - pb.x, 0.f) * fmaxf(pb.w - pb.y, 0.f);
    const float* clsbase = p + ((size_t)b * CH + 4 * BINSc) * HW + hw;
    #pragma unroll 4
    for (int g = 0; g < Gn; g++) {
        float gx1 = sgt[g][0], gy1 = sgt[g][1], gx2 = sgt[g][2], gy2 = sgt[g][3];
        float iw = fmaxf(fminf(gx2, pb.z) - fmaxf(gx1, pb.x), 0.f);
        float ih = fmaxf(fminf(gy2, pb.w) - fmaxf(gy1, pb.y), 0.f);
        float inter = iw * ih;
        float ag = (gx2 - gx1) * (gy2 - gy1);
        float iou = inter / (ag + ap - inter + EPSf);
        bool ing = (cx > gx1) && (cx < gx2) && (cy > gy1) && (cy < gy2);
        float l  = clsbase[(size_t)slab[g] * HW];
        float sc = 1.f / (1.f + expf(-l));
        float i2 = iou * iou;
        float al = sqrtf(sc) * i2 * i2 * i2;
        size_t idx = ((size_t)(b * Gn + g)) * Nn + n;
        g_align[idx]   = al;
        g_overlap[idx] = iou;
        g_ingts[idx]   = ing ? 1 : 0;
        g_mask[idx]    = 0;
    }
}

// top-10 per (b,g) row over masked metric; set mask where value > EPS
__global__ void k_topk()
{
    const int row = blockIdx.x;           // b*Gn + g
    __shared__ float sm[Nn];
    __shared__ float sv[256];
    __shared__ int   si[256];
    size_t off = (size_t)row * Nn;
    int tid = threadIdx.x;
    for (int i = tid; i < Nn; i += 256)
        sm[i] = g_ingts[off + i] ? g_align[off + i] : 0.f;
    __syncthreads();
    for (int it = 0; it < 10; it++) {
        float best = -2.f; int bi = 1 << 30;
        for (int i = tid; i < Nn; i += 256) {
            float v = sm[i];
            if (v > best) { best = v; bi = i; }   // strided ascending -> lowest idx on tie
        }
        sv[tid] = best; si[tid] = bi;
        __syncthreads();
        for (int s = 128; s; s >>= 1) {
            if (tid < s) {
                if (sv[tid + s] > sv[tid] ||
                    (sv[tid + s] == sv[tid] && si[tid + s] < si[tid])) {
                    sv[tid] = sv[tid + s]; si[tid] = si[tid + s];
                }
            }
            __syncthreads();
        }
        float bestv = sv[0]; int bestidx = si[0];
        if (bestv <= EPSf) break;                  // remaining would be filtered anyway
        if (tid == 0) {
            g_mask[off + bestidx] = 1;
            sm[bestidx] = -1.f;
        }
        __syncthreads();
    }
}

// per-anchor: resolve multi-assignment -> is_max; fg, matched, count
__global__ void k_resolve()
{
    int t = blockIdx.x * blockDim.x + threadIdx.x;
    if (t >= Bn * Nn) return;
    int b = t / Nn, n = t % Nn;
    size_t base = ((size_t)b * Gn) * Nn + n;
    int cnt = 0; unsigned bits = 0;
    float bo = -1.f; int bg = 0;
    #pragma unroll 8
    for (int g = 0; g < Gn; g++) {
        size_t idx = base + (size_t)g * Nn;
        if (g_mask[idx]) { cnt++; bits |= (1u << g); }
        float ov = g_overlap[idx];
        if (ov > bo) { bo = ov; bg = g; }
    }
    if (cnt > 1) {
        for (int g = 0; g < Gn; g++)
            g_mask[base + (size_t)g * Nn] = (g == bg) ? 1 : 0;
        bits = 1u << bg;
    }
    bool fg = (bits != 0);
    g_fg[t] = fg ? 1 : 0;
    g_matched[t] = fg ? (__ffs(bits) - 1) : 0;
    if (fg) atomicAdd(&g_cnt, 1);
}

// per (b,g): max over n of masked overlap / masked align
__global__ void k_rowmax()
{
    int row = blockIdx.x;
    size_t off = (size_t)row * Nn;
    int tid = threadIdx.x;
    float mo = 0.f, ma = 0.f;
    for (int i = tid; i < Nn; i += 256) {
        if (g_mask[off + i]) {
            mo = fmaxf(mo, g_overlap[off + i]);
            ma = fmaxf(ma, g_align[off + i]);
        }
    }
    __shared__ float so[256], sa[256];
    so[tid] = mo; sa[tid] = ma;
    __syncthreads();
    for (int s = 128; s; s >>= 1) {
        if (tid < s) {
            so[tid] = fmaxf(so[tid], so[tid + s]);
            sa[tid] = fmaxf(sa[tid], sa[tid + s]);
        }
        __syncthreads();
    }
    if (tid == 0) { g_ovmax[row] = so[0]; g_almax[row] = sa[0]; }
}

// per-fg-anchor: norm, CIoU, DFL loss, focal correction at matched label
__global__ void k_anchor(const float* __restrict__ p0, const float* __restrict__ p1,
                         const float* __restrict__ p2,
                         const float* __restrict__ gtb, const int* __restrict__ gtl)
{
    int t = blockIdx.x * blockDim.x + threadIdx.x;
    double aciou = 0.0, adfl = 0.0, acorr = 0.0;
    if (t < Bn * Nn && g_fg[t]) {
        int b = t / Nn, n = t % Nn;
        const float* p; int hw, W, HW; float stride;
        decode_anchor(n, p, p0, p1, p2, hw, W, HW, stride);
        float cx = ((hw % W) + 0.5f) * stride;
        float cy = ((hw / W) + 0.5f) * stride;
        size_t cbase = ((size_t)b * Gn) * Nn + n;
        int rowb = b * Gn;
        // norm = max_g (align_m * ovmax / (almax + EPS))
        float norm = 0.f;
        for (int g = 0; g < Gn; g++) {
            size_t idx = cbase + (size_t)g * Nn;
            if (g_mask[idx]) {
                float c = g_align[idx] * g_ovmax[rowb + g] / (g_almax[rowb + g] + EPSf);
                norm = fmaxf(norm, c);
            }
        }
        int mg = g_matched[t];
        const float* gb = gtb + ((size_t)(b * Gn + mg)) * 4;
        float tx1 = gb[0], ty1 = gb[1], tx2 = gb[2], ty2 = gb[3];
        float4 pb = g_pred[t];
        // ---- CIoU ----
        float w1 = pb.z - pb.x, h1 = pb.w - pb.y;
        float w2 = tx2 - tx1,   h2 = ty2 - ty1;
        float iw = fmaxf(fminf(pb.z, tx2) - fmaxf(pb.x, tx1), 0.f);
        float ih = fmaxf(fminf(pb.w, ty2) - fmaxf(pb.y, ty1), 0.f);
        float inter = iw * ih;
        float uni = w1 * h1 + w2 * h2 - inter + EPSf;
        float iou = inter / uni;
        float cw  = fmaxf(pb.z, tx2) - fminf(pb.x, tx1);
        float chh = fmaxf(pb.w, ty2) - fminf(pb.y, ty1);
        float c2  = cw * cw + chh * chh + EPSf;
        float dx = pb.x + pb.z - tx1 - tx2;
        float dy = pb.y + pb.w - ty1 - ty2;
        float rho2 = (dx * dx + dy * dy) * 0.25f;
        float dat = atanf(w2 / (h2 + EPSf)) - atanf(w1 / (h1 + EPSf));
        float v = (4.f / (float)(CUDART_PI * CUDART_PI)) * dat * dat;
        float alpha = v / (v - iou + 1.f + EPSf);
        aciou = (double)(1.f - (iou - rho2 / c2 - v * alpha));
        // ---- DFL ----
        const float* base = p + ((size_t)b * CH) * HW + hw;
        float4 lse4 = g_lse[t];
        float lsea[4] = { lse4.x, lse4.y, lse4.z, lse4.w };
        float dd[4] = { fmaxf(cx - tx1, 0.f), fmaxf(cy - ty1, 0.f),
                        fmaxf(tx2 - cx, 0.f), fmaxf(ty2 - cy, 0.f) };
        float sdfl = 0.f;
        #pragma unroll
        for (int s = 0; s < 4; s++) {
            float d = fminf(fmaxf(dd[s] / stride, 0.f), (float)(BINSc - 1) - 1e-6f);
            float lo = floorf(d);
            float a  = d - lo;
            int li = (int)lo;                   // <= 14, so li+1 <= 15
            float llo = base[(size_t)(s * BINSc + li) * HW];
            float lup = base[(size_t)(s * BINSc + li + 1) * HW];
            sdfl -= (1.f - a) * (llo - lsea[s]) + a * (lup - lsea[s]);
        }
        adfl = (double)sdfl;
        // ---- focal correction at matched label ----
        int lab = gtl[b * Gn + mg];
        float l = p[((size_t)b * CH + 4 * BINSc + lab) * HW + hw];
        float pr = 1.f / (1.f + expf(-l));
        float sp = fmaxf(l, 0.f) + log1pf(expf(-fabsf(l)));
        float b0 = 0.75f * pr * pr * sp;        // t = 0 base term
        float tt = norm;
        float ce = fmaxf(l, 0.f) - l * tt + log1pf(expf(-fabsf(l)));
        float pt = pr * tt + (1.f - pr) * (1.f - tt);
        float at = 0.25f * tt + 0.75f * (1.f - tt);
        acorr = (double)(at * (1.f - pt) * (1.f - pt) * ce - b0);
    }
    double r;
    r = blkReduce(aciou); if (threadIdx.x == 0 && r != 0.0) atomicAdd(&g_acc[0], r);
    r = blkReduce(adfl);  if (threadIdx.x == 0 && r != 0.0) atomicAdd(&g_acc[1], r);
    r = blkReduce(acorr); if (threadIdx.x == 0 && r != 0.0) atomicAdd(&g_acc[2], r);
}

// dense focal base (t = 0) over all cls logits of one level
__global__ void k_focal(const float* __restrict__ p, int HW, int total)
{
    int t = blockIdx.x * blockDim.x + threadIdx.x;
    double v = 0.0;
    if (t < total) {
        int b = t / (NCc * HW);
        int r = t % (NCc * HW);
        float l = p[((size_t)b * CH + 4 * BINSc) * HW + r];
        float pr = 1.f / (1.f + expf(-l));
        float sp = fmaxf(l, 0.f) + log1pf(expf(-fabsf(l)));
        v = (double)(0.75f * pr * pr * sp);
    }
    v = blkReduce(v);
    if (threadIdx.x == 0 && v != 0.0) atomicAdd(&g_acc[2], v);
}

__global__ void k_final(float* out)
{
    double den = (double)(g_cnt > 1 ? g_cnt : 1);
    out[0] = (float)(7.5 * g_acc[0] / den);
    out[1] = (float)(1.5 * g_acc[1] / den);
    out[2] = (float)(0.5 * g_acc[2] / den);
}

// ---------------- launch ----------------
extern "C" void kernel_launch(void* const* d_in, const int* in_sizes, int n_in,
                              void* d_out, int out_size)
{
    const float* p0  = (const float*)d_in[0];
    const float* p1  = (const float*)d_in[1];
    const float* p2  = (const float*)d_in[2];
    const float* gtb = (const float*)d_in[3];
    const int*   gtl = (const int*)d_in[4];
    float* out = (float*)d_out;

    const int BN = Bn * Nn;                 // 134400
    const int TB = 256;

    k_init<<<1, 32>>>();
    k_pred<<<(BN + TB - 1) / TB, TB>>>(p0, p1, p2);
    {
        dim3 grid((Nn + TB - 1) / TB, Bn);
        k_pair<<<grid, TB>>>(p0, p1, p2, gtb, gtl);
    }
    k_topk<<<Bn * Gn, TB>>>();
    k_resolve<<<(BN + TB - 1) / TB, TB>>>();
    k_rowmax<<<Bn * Gn, TB>>>();
    k_anchor<<<(BN + TB - 1) / TB, TB>>>(p0, p1, p2, gtb, gtl);
    {
        int t0 = Bn * NCc * 6400;
        int t1 = Bn * NCc * 1600;
        int t2 = Bn * NCc * 400;
        k_focal<<<(t0 + TB - 1) / TB, TB>>>(p0, 6400, t0);
        k_focal<<<(t1 + TB - 1) / TB, TB>>>(p1, 1600, t1);
        k_focal<<<(t2 + TB - 1) / TB, TB>>>(p2, 400,  t2);
    }
    k_final<<<1, 1>>>(out);
}

// round 2
// speedup vs baseline: 1.8645x; 1.8645x over previous
#include <cuda_runtime.h>
#include <cuda_bf16.h>
#include <math.h>
#include <math_constants.h>

#define Bn 16
#define Gn 32
#define Nn 8400
#define NCc 80
#define BINSc 16
#define CH 144          // 4*BINS + NC
#define EPSf 1e-9f
#define MAXCAND 640
#define MAXFG (Bn * Gn * 10)   // 5120

// ---------------- scratch (device globals; no runtime alloc) ----------------
__device__ float4 g_pred[Bn * Nn];            // pred boxes (x1,y1,x2,y2)
__device__ float4 g_lse[Bn * Nn];             // per-side logsumexp of dfl logits
__device__ unsigned int g_bits[Bn * Nn];      // per-anchor gt bitmask
__device__ int    g_topn[Bn * Gn * 10];       // per-row selected anchor indices
__device__ int    g_topcnt[Bn * Gn];
__device__ int    g_ovmax_i[Bn * Gn];         // float-as-int (values >= 0)
__device__ int    g_almax_i[Bn * Gn];
__device__ int    g_fglist[MAXFG];            // t*32 + matched_g
__device__ int    g_cnt;
__device__ double g_acc[3];                   // ciou, dfl, focal

// ---------------- helpers ----------------
__device__ __forceinline__ void decode_anchor(int n, const float*& p,
    const float* p0, const float* p1, const float* p2,
    int& hw, int& W, int& HW, float& stride)
{
    if (n < 6400)      { p = p0; hw = n;        W = 80; HW = 6400; stride = 8.f;  }
    else if (n < 8000) { p = p1; hw = n - 6400; W = 40; HW = 1600; stride = 16.f; }
    else               { p = p2; hw = n - 8000; W = 20; HW = 400;  stride = 32.f; }
}

__device__ __forceinline__ float iou_fn(float4 pb, float gx1, float gy1,
                                        float gx2, float gy2)
{
    float iw = fmaxf(fminf(gx2, pb.z) - fmaxf(gx1, pb.x), 0.f);
    float ih = fmaxf(fminf(gy2, pb.w) - fmaxf(gy1, pb.y), 0.f);
    float inter = iw * ih;
    float ag = (gx2 - gx1) * (gy2 - gy1);
    float ap = fmaxf(pb.z - pb.x, 0.f) * fmaxf(pb.w - pb.y, 0.f);
    return inter / (ag + ap - inter + EPSf);
}

__device__ __forceinline__ float align_fn(float iou, float l)
{
    float sc = 1.f / (1.f + expf(-l));
    float i2 = iou * iou;
    return sqrtf(sc) * i2 * i2 * i2;
}

__device__ __forceinline__ double blkReduce(double v)
{
    __shared__ double sh[8];
    int lane = threadIdx.x & 31, w = threadIdx.x >> 5;
    #pragma unroll
    for (int o = 16; o; o >>= 1) v += __shfl_down_sync(0xffffffffu, v, o);
    if (lane == 0) sh[w] = v;
    __syncthreads();
    v = (threadIdx.x < 8) ? sh[threadIdx.x] : 0.0;
    if (w == 0) {
        #pragma unroll
        for (int o = 4; o; o >>= 1) v += __shfl_down_sync(0xffu, v, o);
    }
    __syncthreads();
    return v;
}

// ---------------- kernels ----------------
__global__ void k_init()
{
    int t = threadIdx.x;
    if (t < 3) g_acc[t] = 0.0;
    if (t == 0) g_cnt = 0;
    if (t < Bn * Gn) { g_ovmax_i[t] = 0; g_almax_i[t] = 0; }
}

// per-anchor: DFL softmax -> dist -> pred box; store per-side logsumexp; zero bits
__global__ void k_pred(const float* __restrict__ p0, const float* __restrict__ p1,
                       const float* __restrict__ p2)
{
    int t = blockIdx.x * blockDim.x + threadIdx.x;
    if (t >= Bn * Nn) return;
    g_bits[t] = 0u;
    int b = t / Nn, n = t % Nn;
    const float* p; int hw, W, HW; float stride;
    decode_anchor(n, p, p0, p1, p2, hw, W, HW, stride);
    const float* base = p + ((size_t)b * CH) * HW + hw;
    float cx = ((hw % W) + 0.5f) * stride;
    float cy = ((hw / W) + 0.5f) * stride;
    float dist[4], lse[4];
    #pragma unroll
    for (int s = 0; s < 4; s++) {
        float l[BINSc], m = -1e30f;
        #pragma unroll
        for (int j = 0; j < BINSc; j++) {
            l[j] = base[(size_t)(s * BINSc + j) * HW];
            m = fmaxf(m, l[j]);
        }
        float sum = 0.f, ws = 0.f;
        #pragma unroll
        for (int j = 0; j < BINSc; j++) {
            float e = expf(l[j] - m);
            sum += e; ws += (float)j * e;
        }
        dist[s] = ws / sum * stride;
        lse[s] = m + logf(sum);
    }
    g_pred[t] = make_float4(cx - dist[0], cy - dist[1], cx + dist[2], cy + dist[3]);
    g_lse[t]  = make_float4(lse[0], lse[1], lse[2], lse[3]);
}

// fused pairwise + top-10 per (b,g) row, sparse candidate list
__global__ void k_pairtopk(const float* __restrict__ p0, const float* __restrict__ p1,
                           const float* __restrict__ p2,
                           const float* __restrict__ gtb, const int* __restrict__ gtl)
{
    const int row = blockIdx.x;            // b*Gn + g
    const int b = row / Gn, g = row % Gn;
    const int tid = threadIdx.x;
    __shared__ float sgx1, sgy1, sgx2, sgy2;
    __shared__ int   slab, scnt;
    __shared__ float scv[MAXCAND];
    __shared__ int   scn[MAXCAND];
    __shared__ float rv[256];
    __shared__ int   ri[256];
    if (tid == 0) {
        const float* gb = gtb + (size_t)row * 4;
        sgx1 = gb[0]; sgy1 = gb[1]; sgx2 = gb[2]; sgy2 = gb[3];
        slab = gtl[row];
        scnt = 0;
    }
    __syncthreads();
    float gx1 = sgx1, gy1 = sgy1, gx2 = sgx2, gy2 = sgy2;
    int lab = slab;
    for (int n = tid; n < Nn; n += 256) {
        const float* p; int hw, W, HW; float stride;
        decode_anchor(n, p, p0, p1, p2, hw, W, HW, stride);
        float cx = ((hw % W) + 0.5f) * stride;
        float cy = ((hw / W) + 0.5f) * stride;
        if (cx > gx1 && cx < gx2 && cy > gy1 && cy < gy2) {
            float4 pb = g_pred[b * Nn + n];
            float iou = iou_fn(pb, gx1, gy1, gx2, gy2);
            float l = p[((size_t)b * CH + 4 * BINSc + lab) * HW + hw];
            float al = align_fn(iou, l);
            if (al > EPSf) {
                int k = atomicAdd(&scnt, 1);
                if (k < MAXCAND) { scv[k] = al; scn[k] = n; }
            }
        }
    }
    __syncthreads();
    int m = min(scnt, MAXCAND);
    int cnt = 0;
    for (int it = 0; it < 10; it++) {
        float best = -1.f; int bn = 0x7fffffff;
        for (int i = tid; i < m; i += 256) {
            float v = scv[i]; int nn = scn[i];
            if (v > best || (v == best && nn < bn)) { best = v; bn = nn; }
        }
        rv[tid] = best; ri[tid] = bn;
        __syncthreads();
        for (int s = 128; s; s >>= 1) {
            if (tid < s) {
                if (rv[tid + s] > rv[tid] ||
                    (rv[tid + s] == rv[tid] && ri[tid + s] < ri[tid])) {
                    rv[tid] = rv[tid + s]; ri[tid] = ri[tid + s];
                }
            }
            __syncthreads();
        }
        float wv = rv[0]; int wn = ri[0];
        if (wv <= EPSf) break;
        for (int i = tid; i < m; i += 256)
            if (scn[i] == wn) scv[i] = -2.f;
        if (tid == 0) {
            g_topn[row * 10 + it] = wn;
            atomicOr(&g_bits[b * Nn + wn], 1u << g);
        }
        cnt++;
        __syncthreads();
    }
    if (tid == 0) g_topcnt[row] = cnt;
}

// per-anchor: resolve multi-assignment via argmax overlap; build compact fg list
__global__ void k_resolve(const float* __restrict__ gtb)
{
    int b = blockIdx.y;
    int n = blockIdx.x * blockDim.x + threadIdx.x;
    __shared__ float sgt[Gn][4];
    if (threadIdx.x < Gn * 4)
        sgt[threadIdx.x / 4][threadIdx.x % 4] = gtb[(size_t)b * Gn * 4 + threadIdx.x];
    __syncthreads();
    if (n >= Nn) return;
    int t = b * Nn + n;
    unsigned int bits = g_bits[t];
    if (__popc(bits) > 1) {
        float4 pb = g_pred[t];
        float bo = -1.f; int bg = 0;
        #pragma unroll 8
        for (int g = 0; g < Gn; g++) {
            float iou = iou_fn(pb, sgt[g][0], sgt[g][1], sgt[g][2], sgt[g][3]);
            if (iou > bo) { bo = iou; bg = g; }
        }
        bits = 1u << bg;
        g_bits[t] = bits;
    }
    if (bits) {
        int mg = __ffs(bits) - 1;
        int pos = atomicAdd(&g_cnt, 1);
        g_fglist[pos] = t * 32 + mg;
    }
}

// per-row masked maxima of align/overlap over the sparse candidate set
__global__ void k_candmax(const float* __restrict__ p0, const float* __restrict__ p1,
                          const float* __restrict__ p2,
                          const float* __restrict__ gtb, const int* __restrict__ gtl)
{
    int row = blockIdx.x;
    int b = row / Gn;
    int tid = threadIdx.x;
    int cnt = g_topcnt[row];
    if (tid >= cnt) return;
    int n = g_topn[row * 10 + tid];
    unsigned int bits = g_bits[b * Nn + n];
    if (!bits) return;
    int gp = __ffs(bits) - 1;
    const float* gb = gtb + ((size_t)(b * Gn + gp)) * 4;
    float gx1 = gb[0], gy1 = gb[1], gx2 = gb[2], gy2 = gb[3];
    int lab = gtl[b * Gn + gp];
    const float* p; int hw, W, HW; float stride;
    decode_anchor(n, p, p0, p1, p2, hw, W, HW, stride);
    float4 pb = g_pred[b * Nn + n];
    float iou = iou_fn(pb, gx1, gy1, gx2, gy2);
    float l = p[((size_t)b * CH + 4 * BINSc + lab) * HW + hw];
    float al = align_fn(iou, l);
    atomicMax(&g_ovmax_i[b * Gn + gp], __float_as_int(iou));
    atomicMax(&g_almax_i[b * Gn + gp], __float_as_int(al));
}

// per-fg-anchor: norm, CIoU, DFL loss, focal correction at matched label
__global__ void k_anchor(const float* __restrict__ p0, const float* __restrict__ p1,
                         const float* __restrict__ p2,
                         const float* __restrict__ gtb, const int* __restrict__ gtl)
{
    int i = blockIdx.x * blockDim.x + threadIdx.x;
    double aciou = 0.0, adfl = 0.0, acorr = 0.0;
    if (i < g_cnt) {
        int code = g_fglist[i];
        int t = code >> 5, mg = code & 31;
        int b = t / Nn, n = t % Nn;
        const float* p; int hw, W, HW; float stride;
        decode_anchor(n, p, p0, p1, p2, hw, W, HW, stride);
        float cx = ((hw % W) + 0.5f) * stride;
        float cy = ((hw / W) + 0.5f) * stride;
        const float* gb = gtb + ((size_t)(b * Gn + mg)) * 4;
        float tx1 = gb[0], ty1 = gb[1], tx2 = gb[2], ty2 = gb[3];
        int lab = gtl[b * Gn + mg];
        float4 pb = g_pred[t];
        // ---- norm ----
        float iou0 = iou_fn(pb, tx1, ty1, tx2, ty2);
        float lcls = p[((size_t)b * CH + 4 * BINSc + lab) * HW + hw];
        float al = align_fn(iou0, lcls);
        float ovmax = __int_as_float(g_ovmax_i[b * Gn + mg]);
        float almax = __int_as_float(g_almax_i[b * Gn + mg]);
        float norm = fmaxf(al * ovmax / (almax + EPSf), 0.f);
        // ---- CIoU ----
        float w1 = pb.z - pb.x, h1 = pb.w - pb.y;
        float w2 = tx2 - tx1,   h2 = ty2 - ty1;
        float iw = fmaxf(fminf(pb.z, tx2) - fmaxf(pb.x, tx1), 0.f);
        float ih = fmaxf(fminf(pb.w, ty2) - fmaxf(pb.y, ty1), 0.f);
        float inter = iw * ih;
        float uni = w1 * h1 + w2 * h2 - inter + EPSf;
        float iou = inter / uni;
        float cw  = fmaxf(pb.z, tx2) - fminf(pb.x, tx1);
        float chh = fmaxf(pb.w, ty2) - fminf(pb.y, ty1);
        float c2  = cw * cw + chh * chh + EPSf;
        float dx = pb.x + pb.z - tx1 - tx2;
        float dy = pb.y + pb.w - ty1 - ty2;
        float rho2 = (dx * dx + dy * dy) * 0.25f;
        float dat = atanf(w2 / (h2 + EPSf)) - atanf(w1 / (h1 + EPSf));
        float v = (4.f / (float)(CUDART_PI * CUDART_PI)) * dat * dat;
        float alpha = v / (v - iou + 1.f + EPSf);
        aciou = (double)(1.f - (iou - rho2 / c2 - v * alpha));
        // ---- DFL ----
        const float* base = p + ((size_t)b * CH) * HW + hw;
        float4 lse4 = g_lse[t];
        float lsea[4] = { lse4.x, lse4.y, lse4.z, lse4.w };
        float dd[4] = { fmaxf(cx - tx1, 0.f), fmaxf(cy - ty1, 0.f),
                        fmaxf(tx2 - cx, 0.f), fmaxf(ty2 - cy, 0.f) };
        float sdfl = 0.f;
        #pragma unroll
        for (int s = 0; s < 4; s++) {
            float d = fminf(fmaxf(dd[s] / stride, 0.f), (float)(BINSc - 1) - 1e-6f);
            float lo = floorf(d);
            float a  = d - lo;
            int li = (int)lo;
            float llo = base[(size_t)(s * BINSc + li) * HW];
            float lup = base[(size_t)(s * BINSc + li + 1) * HW];
            sdfl -= (1.f - a) * (llo - lsea[s]) + a * (lup - lsea[s]);
        }
        adfl = (double)sdfl;
        // ---- focal correction at matched label ----
        float l = lcls;
        float pr = 1.f / (1.f + expf(-l));
        float sp = fmaxf(l, 0.f) + log1pf(expf(-fabsf(l)));
        float b0 = 0.75f * pr * pr * sp;        // t = 0 base term
        float tt = norm;
        float ce = fmaxf(l, 0.f) - l * tt + log1pf(expf(-fabsf(l)));
        float pt = pr * tt + (1.f - pr) * (1.f - tt);
        float at = 0.25f * tt + 0.75f * (1.f - tt);
        acorr = (double)(at * (1.f - pt) * (1.f - pt) * ce - b0);
    }
    double r;
    r = blkReduce(aciou); if (threadIdx.x == 0 && r != 0.0) atomicAdd(&g_acc[0], r);
    r = blkReduce(adfl);  if (threadIdx.x == 0 && r != 0.0) atomicAdd(&g_acc[1], r);
    r = blkReduce(acorr); if (threadIdx.x == 0 && r != 0.0) atomicAdd(&g_acc[2], r);
}

// dense focal base (t = 0) over all cls logits, all 3 levels, float4
__global__ void k_focal(const float* __restrict__ p0, const float* __restrict__ p1,
                        const float* __restrict__ p2)
{
    const int L0 = Bn * NCc * 6400 / 4;   // 2,048,000
    const int L1 = Bn * NCc * 1600 / 4;   // 512,000
    const int L2 = Bn * NCc * 400 / 4;    // 128,000
    int t = blockIdx.x * blockDim.x + threadIdx.x;
    double v = 0.0;
    const float* p = 0; int HW = 0; int e = 0; bool valid = true;
    if (t < L0)            { p = p0; HW = 6400; e = t; }
    else if (t < L0 + L1)  { p = p1; HW = 1600; e = t - L0; }
    else if (t < L0 + L1 + L2) { p = p2; HW = 400; e = t - L0 - L1; }
    else valid = false;
    if (valid) {
        int per = NCc * HW / 4;
        int b = e / per, r = e % per;
        const float4* base = (const float4*)(p + ((size_t)b * CH + 4 * BINSc) * HW);
        float4 x = base[r];
        float l, pr, sp;
        l = x.x; pr = 1.f / (1.f + expf(-l)); sp = fmaxf(l, 0.f) + log1pf(expf(-fabsf(l)));
        v += (double)(0.75f * pr * pr * sp);
        l = x.y; pr = 1.f / (1.f + expf(-l)); sp = fmaxf(l, 0.f) + log1pf(expf(-fabsf(l)));
        v += (double)(0.75f * pr * pr * sp);
        l = x.z; pr = 1.f / (1.f + expf(-l)); sp = fmaxf(l, 0.f) + log1pf(expf(-fabsf(l)));
        v += (double)(0.75f * pr * pr * sp);
        l = x.w; pr = 1.f / (1.f + expf(-l)); sp = fmaxf(l, 0.f) + log1pf(expf(-fabsf(l)));
        v += (double)(0.75f * pr * pr * sp);
    }
    v = blkReduce(v);
    if (threadIdx.x == 0 && v != 0.0) atomicAdd(&g_acc[2], v);
}

__global__ void k_final(float* out)
{
    double den = (double)(g_cnt > 1 ? g_cnt : 1);
    out[0] = (float)(7.5 * g_acc[0] / den);
    out[1] = (float)(1.5 * g_acc[1] / den);
    out[2] = (float)(0.5 * g_acc[2] / den);
}

// ---------------- launch ----------------
extern "C" void kernel_launch(void* const* d_in, const int* in_sizes, int n_in,
                              void* d_out, int out_size)
{
    const float* p0  = (const float*)d_in[0];
    const float* p1  = (const float*)d_in[1];
    const float* p2  = (const float*)d_in[2];
    const float* gtb = (const float*)d_in[3];
    const int*   gtl = (const int*)d_in[4];
    float* out = (float*)d_out;

    const int BN = Bn * Nn;                 // 134400
    const int TB = 256;

    k_init<<<1, 512>>>();
    k_pred<<<(BN + TB - 1) / TB, TB>>>(p0, p1, p2);
    k_pairtopk<<<Bn * Gn, TB>>>(p0, p1, p2, gtb, gtl);
    {
        dim3 grid((Nn + TB - 1) / TB, Bn);
        k_resolve<<<grid, TB>>>(gtb);
    }
    k_candmax<<<Bn * Gn, 16>>>(p0, p1, p2, gtb, gtl);
    k_anchor<<<MAXFG / TB, TB>>>(p0, p1, p2, gtb, gtl);
    {
        int total4 = (Bn * NCc * (6400 + 1600 + 400)) / 4;   // 2,688,000
        k_focal<<<(total4 + TB - 1) / TB, TB>>>(p0, p1, p2);
    }
    k_final<<<1, 1>>>(out);
}

// round 3
// speedup vs baseline: 1.9519x; 1.0469x over previous
#include <cuda_runtime.h>
#include <cuda_bf16.h>
#include <math.h>
#include <math_constants.h>

#define Bn 16
#define Gn 32
#define Nn 8400
#define NCc 80
#define BINSc 16
#define CH 144          // 4*BINS + NC
#define EPSf 1e-9f
#define MAXCAND 1024
#define MAXFG (Bn * Gn * 10)   // 5120

// ---------------- scratch (device globals; no runtime alloc) ----------------
__device__ float4 g_pred[Bn * Nn];            // pred boxes (x1,y1,x2,y2)
__device__ float4 g_lse[Bn * Nn];             // per-side logsumexp of dfl logits
__device__ unsigned int g_bits[Bn * Nn];      // per-anchor gt bitmask
__device__ int    g_claim[Bn * Nn];           // dedup flag for resolve
__device__ int    g_topn[Bn * Gn * 10];       // per-row selected anchor indices
__device__ int    g_topcnt[Bn * Gn];
__device__ int    g_ovmax_i[Bn * Gn];         // float-as-int (values >= 0)
__device__ int    g_almax_i[Bn * Gn];
__device__ int    g_fglist[MAXFG];            // t*32 + matched_g
__device__ int    g_cnt;
__device__ double g_acc[3];                   // ciou, dfl, focal

__constant__ int   c_base[3]   = { 0, 6400, 8000 };
__constant__ int   c_W[3]      = { 80, 40, 20 };
__constant__ float c_stride[3] = { 8.f, 16.f, 32.f };

// ---------------- helpers ----------------
__device__ __forceinline__ void decode_anchor(int n, const float*& p,
    const float* p0, const float* p1, const float* p2,
    int& hw, int& W, int& HW, float& stride)
{
    if (n < 6400)      { p = p0; hw = n;        W = 80; HW = 6400; stride = 8.f;  }
    else if (n < 8000) { p = p1; hw = n - 6400; W = 40; HW = 1600; stride = 16.f; }
    else               { p = p2; hw = n - 8000; W = 20; HW = 400;  stride = 32.f; }
}

__device__ __forceinline__ float iou_fn(float4 pb, float gx1, float gy1,
                                        float gx2, float gy2)
{
    float iw = fmaxf(fminf(gx2, pb.z) - fmaxf(gx1, pb.x), 0.f);
    float ih = fmaxf(fminf(gy2, pb.w) - fmaxf(gy1, pb.y), 0.f);
    float inter = iw * ih;
    float ag = (gx2 - gx1) * (gy2 - gy1);
    float ap = fmaxf(pb.z - pb.x, 0.f) * fmaxf(pb.w - pb.y, 0.f);
    return inter / (ag + ap - inter + EPSf);
}

__device__ __forceinline__ float align_fn(float iou, float l)
{
    float sc = 1.f / (1.f + expf(-l));
    float i2 = iou * iou;
    return sqrtf(sc) * i2 * i2 * i2;
}

__device__ __forceinline__ double blkReduce(double v)
{
    __shared__ double sh[8];
    int lane = threadIdx.x & 31, w = threadIdx.x >> 5;
    #pragma unroll
    for (int o = 16; o; o >>= 1) v += __shfl_down_sync(0xffffffffu, v, o);
    if (lane == 0) sh[w] = v;
    __syncthreads();
    v = (threadIdx.x < 8) ? sh[threadIdx.x] : 0.0;
    if (w == 0) {
        #pragma unroll
        for (int o = 4; o; o >>= 1) v += __shfl_down_sync(0xffu, v, o);
    }
    __syncthreads();
    return v;
}

// ---------------- kernels ----------------
__global__ void k_init()
{
    int t = threadIdx.x;
    if (t < 3) g_acc[t] = 0.0;
    if (t == 0) g_cnt = 0;
    if (t < Bn * Gn) { g_ovmax_i[t] = 0; g_almax_i[t] = 0; }
}

// per-anchor: DFL softmax -> dist -> pred box; store lse; zero bits/claim
__global__ void k_pred(const float* __restrict__ p0, const float* __restrict__ p1,
                       const float* __restrict__ p2)
{
    int t = blockIdx.x * blockDim.x + threadIdx.x;
    if (t >= Bn * Nn) return;
    g_bits[t] = 0u;
    g_claim[t] = 0;
    int b = t / Nn, n = t % Nn;
    const float* p; int hw, W, HW; float stride;
    decode_anchor(n, p, p0, p1, p2, hw, W, HW, stride);
    const float* base = p + ((size_t)b * CH) * HW + hw;
    float cx = ((hw % W) + 0.5f) * stride;
    float cy = ((hw / W) + 0.5f) * stride;
    float dist[4], lse[4];
    #pragma unroll
    for (int s = 0; s < 4; s++) {
        float l[BINSc], m = -1e30f;
        #pragma unroll
        for (int j = 0; j < BINSc; j++) {
            l[j] = base[(size_t)(s * BINSc + j) * HW];
            m = fmaxf(m, l[j]);
        }
        float sum = 0.f, ws = 0.f;
        #pragma unroll
        for (int j = 0; j < BINSc; j++) {
            float e = expf(l[j] - m);
            sum += e; ws += (float)j * e;
        }
        dist[s] = ws / sum * stride;
        lse[s] = m + logf(sum);
    }
    g_pred[t] = make_float4(cx - dist[0], cy - dist[1], cx + dist[2], cy + dist[3]);
    g_lse[t]  = make_float4(lse[0], lse[1], lse[2], lse[3]);
}

// fused pairwise + top-10 per (b,g) row; closed-form in-box rect enumeration
__global__ void k_pairtopk(const float* __restrict__ p0, const float* __restrict__ p1,
                           const float* __restrict__ p2,
                           const float* __restrict__ gtb, const int* __restrict__ gtl)
{
    const int row = blockIdx.x;            // b*Gn + g
    const int b = row / Gn, g = row % Gn;
    const int tid = threadIdx.x;
    __shared__ float sgx1, sgy1, sgx2, sgy2;
    __shared__ int   slab, scnt;
    __shared__ float scv[MAXCAND];
    __shared__ int   scn[MAXCAND];
    __shared__ float rv[256];
    __shared__ int   ri[256];
    if (tid == 0) {
        const float* gb = gtb + (size_t)row * 4;
        sgx1 = gb[0]; sgy1 = gb[1]; sgx2 = gb[2]; sgy2 = gb[3];
        slab = gtl[row];
        scnt = 0;
    }
    __syncthreads();
    const float gx1 = sgx1, gy1 = sgy1, gx2 = sgx2, gy2 = sgy2;
    const int lab = slab;
    const float* const pp[3] = { p0, p1, p2 };

    // per-level in-box rectangles (with ±1 margin; exact test inside)
    int jx0[3], nx[3], jy0[3], ny[3], pre[4];
    pre[0] = 0;
    #pragma unroll
    for (int l = 0; l < 3; l++) {
        float s = c_stride[l]; int W = c_W[l];
        int x0 = max(0, (int)floorf(gx1 / s - 0.5f));
        int x1 = min(W - 1, (int)ceilf (gx2 / s - 0.5f));
        int y0 = max(0, (int)floorf(gy1 / s - 0.5f));
        int y1 = min(W - 1, (int)ceilf (gy2 / s - 0.5f));
        jx0[l] = x0; nx[l] = max(0, x1 - x0 + 1);
        jy0[l] = y0; ny[l] = max(0, y1 - y0 + 1);
        pre[l + 1] = pre[l] + nx[l] * ny[l];
    }
    const int total = pre[3];

    for (int idx = tid; idx < total; idx += 256) {
        int l = (idx >= pre[1]) + (idx >= pre[2]);
        int e = idx - pre[l];
        int iy = e / nx[l], ix = e - iy * nx[l];
        int j = jx0[l] + ix, i = jy0[l] + iy;
        float s = c_stride[l];
        float cx = (j + 0.5f) * s;
        float cy = (i + 0.5f) * s;
        if (cx > gx1 && cx < gx2 && cy > gy1 && cy < gy2) {
            int W = c_W[l];
            int HW = W * W;
            int hw = i * W + j;
            int n = c_base[l] + hw;
            float4 pb = g_pred[b * Nn + n];
            float iou = iou_fn(pb, gx1, gy1, gx2, gy2);
            float lg = pp[l][((size_t)b * CH + 4 * BINSc + lab) * HW + hw];
            float al = align_fn(iou, lg);
            if (al > EPSf) {
                int k = atomicAdd(&scnt, 1);
                if (k < MAXCAND) { scv[k] = al; scn[k] = n; }
            }
        }
    }
    __syncthreads();
    int m = min(scnt, MAXCAND);
    int cnt = 0;
    for (int it = 0; it < 10; it++) {
        float best = -1.f; int bn = 0x7fffffff;
        for (int i = tid; i < m; i += 256) {
            float v = scv[i]; int nn = scn[i];
            if (v > best || (v == best && nn < bn)) { best = v; bn = nn; }
        }
        rv[tid] = best; ri[tid] = bn;
        __syncthreads();
        for (int s = 128; s; s >>= 1) {
            if (tid < s) {
                if (rv[tid + s] > rv[tid] ||
                    (rv[tid + s] == rv[tid] && ri[tid + s] < ri[tid])) {
                    rv[tid] = rv[tid + s]; ri[tid] = ri[tid + s];
                }
            }
            __syncthreads();
        }
        float wv = rv[0]; int wn = ri[0];
        if (wv <= EPSf) break;
        for (int i = tid; i < m; i += 256)
            if (scn[i] == wn) scv[i] = -2.f;
        if (tid == 0) {
            g_topn[row * 10 + it] = wn;
            atomicOr(&g_bits[b * Nn + wn], 1u << g);
        }
        cnt++;
        __syncthreads();
    }
    if (tid == 0) g_topcnt[row] = cnt;
}

// sparse resolve over topn entries + fused row-max (candmax)
__global__ void k_resolve(const float* __restrict__ p0, const float* __restrict__ p1,
                          const float* __restrict__ p2,
                          const float* __restrict__ gtb, const int* __restrict__ gtl)
{
    int e = blockIdx.x * blockDim.x + threadIdx.x;
    if (e >= Bn * Gn * 10) return;
    int row = e / 10, slot = e % 10;
    if (slot >= g_topcnt[row]) return;
    int b = row / Gn;
    int n = g_topn[row * 10 + slot];
    int t = b * Nn + n;
    if (atomicExch(&g_claim[t], 1)) return;      // already processed
    unsigned int bits = g_bits[t];
    float4 pb = g_pred[t];
    int mg;
    if (__popc(bits) > 1) {
        const float* gbase = gtb + (size_t)b * Gn * 4;
        float bo = -1.f; int bg = 0;
        #pragma unroll 8
        for (int g = 0; g < Gn; g++) {
            float iou = iou_fn(pb, gbase[g * 4 + 0], gbase[g * 4 + 1],
                               gbase[g * 4 + 2], gbase[g * 4 + 3]);
            if (iou > bo) { bo = iou; bg = g; }
        }
        mg = bg;
    } else {
        mg = __ffs(bits) - 1;
    }
    int pos = atomicAdd(&g_cnt, 1);
    g_fglist[pos] = t * 32 + mg;
    // fused row-max of align/overlap for the matched row
    const float* gb = gtb + ((size_t)(b * Gn + mg)) * 4;
    float gx1 = gb[0], gy1 = gb[1], gx2 = gb[2], gy2 = gb[3];
    int lab = gtl[b * Gn + mg];
    const float* p; int hw, W, HW; float stride;
    decode_anchor(n, p, p0, p1, p2, hw, W, HW, stride);
    float iou = iou_fn(pb, gx1, gy1, gx2, gy2);
    float l = p[((size_t)b * CH + 4 * BINSc + lab) * HW + hw];
    float al = align_fn(iou, l);
    atomicMax(&g_ovmax_i[b * Gn + mg], __float_as_int(iou));
    atomicMax(&g_almax_i[b * Gn + mg], __float_as_int(al));
}

// per-fg-anchor: norm, CIoU, DFL loss, focal correction at matched label
__global__ void k_anchor(const float* __restrict__ p0, const float* __restrict__ p1,
                         const float* __restrict__ p2,
                         const float* __restrict__ gtb, const int* __restrict__ gtl)
{
    int i = blockIdx.x * blockDim.x + threadIdx.x;
    double aciou = 0.0, adfl = 0.0, acorr = 0.0;
    if (i < g_cnt) {
        int code = g_fglist[i];
        int t = code >> 5, mg = code & 31;
        int b = t / Nn, n = t % Nn;
        const float* p; int hw, W, HW; float stride;
        decode_anchor(n, p, p0, p1, p2, hw, W, HW, stride);
        float cx = ((hw % W) + 0.5f) * stride;
        float cy = ((hw / W) + 0.5f) * stride;
        const float* gb = gtb + ((size_t)(b * Gn + mg)) * 4;
        float tx1 = gb[0], ty1 = gb[1], tx2 = gb[2], ty2 = gb[3];
        int lab = gtl[b * Gn + mg];
        float4 pb = g_pred[t];
        // ---- norm ----
        float iou0 = iou_fn(pb, tx1, ty1, tx2, ty2);
        float lcls = p[((size_t)b * CH + 4 * BINSc + lab) * HW + hw];
        float al = align_fn(iou0, lcls);
        float ovmax = __int_as_float(g_ovmax_i[b * Gn + mg]);
        float almax = __int_as_float(g_almax_i[b * Gn + mg]);
        float norm = fmaxf(al * ovmax / (almax + EPSf), 0.f);
        // ---- CIoU ----
        float w1 = pb.z - pb.x, h1 = pb.w - pb.y;
        float w2 = tx2 - tx1,   h2 = ty2 - ty1;
        float iw = fmaxf(fminf(pb.z, tx2) - fmaxf(pb.x, tx1), 0.f);
        float ih = fmaxf(fminf(pb.w, ty2) - fmaxf(pb.y, ty1), 0.f);
        float inter = iw * ih;
        float uni = w1 * h1 + w2 * h2 - inter + EPSf;
        float iou = inter / uni;
        float cw  = fmaxf(pb.z, tx2) - fminf(pb.x, tx1);
        float chh = fmaxf(pb.w, ty2) - fminf(pb.y, ty1);
        float c2  = cw * cw + chh * chh + EPSf;
        float dx = pb.x + pb.z - tx1 - tx2;
        float dy = pb.y + pb.w - ty1 - ty2;
        float rho2 = (dx * dx + dy * dy) * 0.25f;
        float dat = atanf(w2 / (h2 + EPSf)) - atanf(w1 / (h1 + EPSf));
        float v = (4.f / (float)(CUDART_PI * CUDART_PI)) * dat * dat;
        float alpha = v / (v - iou + 1.f + EPSf);
        aciou = (double)(1.f - (iou - rho2 / c2 - v * alpha));
        // ---- DFL ----
        const float* base = p + ((size_t)b * CH) * HW + hw;
        float4 lse4 = g_lse[t];
        float lsea[4] = { lse4.x, lse4.y, lse4.z, lse4.w };
        float dd[4] = { fmaxf(cx - tx1, 0.f), fmaxf(cy - ty1, 0.f),
                        fmaxf(tx2 - cx, 0.f), fmaxf(ty2 - cy, 0.f) };
        float sdfl = 0.f;
        #pragma unroll
        for (int s = 0; s < 4; s++) {
            float d = fminf(fmaxf(dd[s] / stride, 0.f), (float)(BINSc - 1) - 1e-6f);
            float lo = floorf(d);
            float a  = d - lo;
            int li = (int)lo;
            float llo = base[(size_t)(s * BINSc + li) * HW];
            float lup = base[(size_t)(s * BINSc + li + 1) * HW];
            sdfl -= (1.f - a) * (llo - lsea[s]) + a * (lup - lsea[s]);
        }
        adfl = (double)sdfl;
        // ---- focal correction at matched label ----
        float l = lcls;
        float pr = 1.f / (1.f + expf(-l));
        float sp = fmaxf(l, 0.f) + log1pf(expf(-fabsf(l)));
        float b0 = 0.75f * pr * pr * sp;        // t = 0 base term
        float tt = norm;
        float ce = fmaxf(l, 0.f) - l * tt + log1pf(expf(-fabsf(l)));
        float pt = pr * tt + (1.f - pr) * (1.f - tt);
        float at = 0.25f * tt + 0.75f * (1.f - tt);
        acorr = (double)(at * (1.f - pt) * (1.f - pt) * ce - b0);
    }
    double r;
    r = blkReduce(aciou); if (threadIdx.x == 0 && r != 0.0) atomicAdd(&g_acc[0], r);
    r = blkReduce(adfl);  if (threadIdx.x == 0 && r != 0.0) atomicAdd(&g_acc[1], r);
    r = blkReduce(acorr); if (threadIdx.x == 0 && r != 0.0) atomicAdd(&g_acc[2], r);
}

// dense focal base (t = 0) over all cls logits, all 3 levels, float4
__global__ void k_focal(const float* __restrict__ p0, const float* __restrict__ p1,
                        const float* __restrict__ p2)
{
    const int L0 = Bn * NCc * 6400 / 4;   // 2,048,000
    const int L1 = Bn * NCc * 1600 / 4;   // 512,000
    const int L2 = Bn * NCc * 400 / 4;    // 128,000
    int t = blockIdx.x * blockDim.x + threadIdx.x;
    double v = 0.0;
    const float* p = 0; int HW = 0; int e = 0; bool valid = true;
    if (t < L0)            { p = p0; HW = 6400; e = t; }
    else if (t < L0 + L1)  { p = p1; HW = 1600; e = t - L0; }
    else if (t < L0 + L1 + L2) { p = p2; HW = 400; e = t - L0 - L1; }
    else valid = false;
    if (valid) {
        int per = NCc * HW / 4;
        int b = e / per, r = e % per;
        const float4* base = (const float4*)(p + ((size_t)b * CH + 4 * BINSc) * HW);
        float4 x = base[r];
        float l, pr, sp;
        l = x.x; pr = 1.f / (1.f + expf(-l)); sp = fmaxf(l, 0.f) + log1pf(expf(-fabsf(l)));
        v += (double)(0.75f * pr * pr * sp);
        l = x.y; pr = 1.f / (1.f + expf(-l)); sp = fmaxf(l, 0.f) + log1pf(expf(-fabsf(l)));
        v += (double)(0.75f * pr * pr * sp);
        l = x.z; pr = 1.f / (1.f + expf(-l)); sp = fmaxf(l, 0.f) + log1pf(expf(-fabsf(l)));
        v += (double)(0.75f * pr * pr * sp);
        l = x.w; pr = 1.f / (1.f + expf(-l)); sp = fmaxf(l, 0.f) + log1pf(expf(-fabsf(l)));
        v += (double)(0.75f * pr * pr * sp);
    }
    v = blkReduce(v);
    if (threadIdx.x == 0 && v != 0.0) atomicAdd(&g_acc[2], v);
}

__global__ void k_final(float* out)
{
    double den = (double)(g_cnt > 1 ? g_cnt : 1);
    out[0] = (float)(7.5 * g_acc[0] / den);
    out[1] = (float)(1.5 * g_acc[1] / den);
    out[2] = (float)(0.5 * g_acc[2] / den);
}

// ---------------- launch ----------------
extern "C" void kernel_launch(void* const* d_in, const int* in_sizes, int n_in,
                              void* d_out, int out_size)
{
    const float* p0  = (const float*)d_in[0];
    const float* p1  = (const float*)d_in[1];
    const float* p2  = (const float*)d_in[2];
    const float* gtb = (const float*)d_in[3];
    const int*   gtl = (const int*)d_in[4];
    float* out = (float*)d_out;

    const int BN = Bn * Nn;                 // 134400
    const int TB = 256;

    k_init<<<1, 512>>>();
    k_pred<<<(BN + TB - 1) / TB, TB>>>(p0, p1, p2);
    k_pairtopk<<<Bn * Gn, TB>>>(p0, p1, p2, gtb, gtl);
    k_resolve<<<MAXFG / TB, TB>>>(p0, p1, p2, gtb, gtl);
    k_anchor<<<MAXFG / TB, TB>>>(p0, p1, p2, gtb, gtl);
    {
        int total4 = (Bn * NCc * (6400 + 1600 + 400)) / 4;   // 2,688,000
        k_focal<<<(total4 + TB - 1) / TB, TB>>>(p0, p1, p2);
    }
    k_final<<<1, 1>>>(out);
}

// round 4
// speedup vs baseline: 2.3865x; 1.2226x over previous
#include <cuda_runtime.h>
#include <cuda_bf16.h>
#include <math.h>
#include <math_constants.h>

#define Bn 16
#define Gn 32
#define Nn 8400
#define NCc 80
#define BINSc 16
#define CH 144          // 4*BINS + NC
#define EPSf 1e-9f
#define MAXFG (Bn * Gn * 10)   // 5120

// ---------------- scratch (device globals; zero-init at load) ----------------
__device__ float4 g_pred[Bn * Nn];            // pred boxes (x1,y1,x2,y2)
__device__ float4 g_lse[Bn * Nn];             // per-side logsumexp of dfl logits
__device__ unsigned int g_bits[Bn * Nn];      // per-anchor gt bitmask
__device__ int    g_claim[Bn * Nn];           // dedup flag (self-cleaning)
__device__ int    g_topn[Bn * Gn * 10];       // per-row selected anchor indices
__device__ int    g_topcnt[Bn * Gn];
__device__ int    g_ovmax_i[Bn * Gn];         // float-as-int (>=0); reset by k_final
__device__ int    g_almax_i[Bn * Gn];
__device__ int    g_fglist[MAXFG];            // t*32 + matched_g
__device__ int    g_cnt;                      // reset by k_final
__device__ double g_acc[3];                   // ciou, dfl, focal; reset by k_final

__constant__ int   c_base[3]   = { 0, 6400, 8000 };
__constant__ int   c_W[3]      = { 80, 40, 20 };
__constant__ float c_stride[3] = { 8.f, 16.f, 32.f };

// ---------------- helpers ----------------
__device__ __forceinline__ void decode_anchor(int n, const float*& p,
    const float* p0, const float* p1, const float* p2,
    int& hw, int& W, int& HW, float& stride)
{
    if (n < 6400)      { p = p0; hw = n;        W = 80; HW = 6400; stride = 8.f;  }
    else if (n < 8000) { p = p1; hw = n - 6400; W = 40; HW = 1600; stride = 16.f; }
    else               { p = p2; hw = n - 8000; W = 20; HW = 400;  stride = 32.f; }
}

__device__ __forceinline__ float iou_fn(float4 pb, float gx1, float gy1,
                                        float gx2, float gy2)
{
    float iw = fmaxf(fminf(gx2, pb.z) - fmaxf(gx1, pb.x), 0.f);
    float ih = fmaxf(fminf(gy2, pb.w) - fmaxf(gy1, pb.y), 0.f);
    float inter = iw * ih;
    float ag = (gx2 - gx1) * (gy2 - gy1);
    float ap = fmaxf(pb.z - pb.x, 0.f) * fmaxf(pb.w - pb.y, 0.f);
    return inter / (ag + ap - inter + EPSf);
}

__device__ __forceinline__ float align_fn(float iou, float l)
{
    float sc = 1.f / (1.f + expf(-l));
    float i2 = iou * iou;
    return sqrtf(sc) * i2 * i2 * i2;
}

__device__ __forceinline__ float focal_base(float l)   // t = 0 term
{
    float pr = 1.f / (1.f + expf(-l));
    float sp = fmaxf(l, 0.f) + log1pf(expf(-fabsf(l)));
    return 0.75f * pr * pr * sp;
}

__device__ __forceinline__ double blkReduce(double v)  // blockDim.x == 256
{
    __shared__ double sh[8];
    int lane = threadIdx.x & 31, w = threadIdx.x >> 5;
    #pragma unroll
    for (int o = 16; o; o >>= 1) v += __shfl_down_sync(0xffffffffu, v, o);
    if (lane == 0) sh[w] = v;
    __syncthreads();
    v = (threadIdx.x < 8) ? sh[threadIdx.x] : 0.0;
    if (w == 0) {
        #pragma unroll
        for (int o = 4; o; o >>= 1) v += __shfl_down_sync(0xffu, v, o);
    }
    __syncthreads();
    return v;
}

// ---------------- kernels ----------------

// per-anchor: DFL softmax -> pred box + lse; zero bits; FUSED focal base sum
__global__ void k_pred(const float* __restrict__ p0, const float* __restrict__ p1,
                       const float* __restrict__ p2)
{
    int t = blockIdx.x * blockDim.x + threadIdx.x;   // grid covers exactly Bn*Nn
    g_bits[t] = 0u;
    int b = t / Nn, n = t % Nn;
    const float* p; int hw, W, HW; float stride;
    decode_anchor(n, p, p0, p1, p2, hw, W, HW, stride);
    const float* base = p + ((size_t)b * CH) * HW + hw;
    float cx = ((hw % W) + 0.5f) * stride;
    float cy = ((hw / W) + 0.5f) * stride;
    float dist[4], lse[4];
    #pragma unroll
    for (int s = 0; s < 4; s++) {
        float l[BINSc], m = -1e30f;
        #pragma unroll
        for (int j = 0; j < BINSc; j++) {
            l[j] = base[(size_t)(s * BINSc + j) * HW];
            m = fmaxf(m, l[j]);
        }
        float sum = 0.f, ws = 0.f;
        #pragma unroll
        for (int j = 0; j < BINSc; j++) {
            float e = expf(l[j] - m);
            sum += e; ws += (float)j * e;
        }
        dist[s] = ws / sum * stride;
        lse[s] = m + logf(sum);
    }
    g_pred[t] = make_float4(cx - dist[0], cy - dist[1], cx + dist[2], cy + dist[3]);
    g_lse[t]  = make_float4(lse[0], lse[1], lse[2], lse[3]);

    // fused focal base (t=0) over this anchor's 80 cls logits
    const float* cls = base + (size_t)(4 * BINSc) * HW;
    double fsum = 0.0;
    #pragma unroll 4
    for (int c = 0; c < NCc; c++)
        fsum += (double)focal_base(cls[(size_t)c * HW]);
    fsum = blkReduce(fsum);
    if (threadIdx.x == 0) atomicAdd(&g_acc[2], fsum);
}

// one WARP per (b,g) row: rect enumeration + register top-10 + warp merge
__global__ void k_pairtopk(const float* __restrict__ p0, const float* __restrict__ p1,
                           const float* __restrict__ p2,
                           const float* __restrict__ gtb, const int* __restrict__ gtl)
{
    int warp = (blockIdx.x * blockDim.x + threadIdx.x) >> 5;
    if (warp >= Bn * Gn) return;
    const int lane = threadIdx.x & 31;
    const int row = warp, b = row >> 5, g = row & 31;
    const float gx1 = gtb[row * 4 + 0], gy1 = gtb[row * 4 + 1];
    const float gx2 = gtb[row * 4 + 2], gy2 = gtb[row * 4 + 3];
    const int lab = gtl[row];
    const float* const pp[3] = { p0, p1, p2 };

    int jx0[3], nx[3], jy0[3], pre[4];
    pre[0] = 0;
    #pragma unroll
    for (int l = 0; l < 3; l++) {
        float s = c_stride[l]; int W = c_W[l];
        int x0 = max(0, (int)floorf(gx1 / s - 0.5f));
        int x1 = min(W - 1, (int)ceilf (gx2 / s - 0.5f));
        int y0 = max(0, (int)floorf(gy1 / s - 0.5f));
        int y1 = min(W - 1, (int)ceilf (gy2 / s - 0.5f));
        jx0[l] = x0; nx[l] = max(0, x1 - x0 + 1);
        jy0[l] = y0; int nyl = max(0, y1 - y0 + 1);
        pre[l + 1] = pre[l] + nx[l] * nyl;
    }
    const int total = pre[3];

    // register-resident sorted top-10 (desc by value, asc by index on ties)
    float val[10]; int idx[10];
    #pragma unroll
    for (int k = 0; k < 10; k++) { val[k] = 0.f; idx[k] = 0x7fffffff; }

    for (int c = lane; c < total; c += 32) {
        int l = (c >= pre[1]) + (c >= pre[2]);
        int e = c - pre[l];
        int iy = e / nx[l], ix = e - iy * nx[l];
        int j = jx0[l] + ix, i = jy0[l] + iy;
        float s = c_stride[l];
        float cx = (j + 0.5f) * s;
        float cy = (i + 0.5f) * s;
        if (!(cx > gx1 && cx < gx2 && cy > gy1 && cy < gy2)) continue;
        int W = c_W[l], HW = W * W;
        int hw = i * W + j;
        int n = c_base[l] + hw;
        float4 pb = g_pred[b * Nn + n];
        float iou = iou_fn(pb, gx1, gy1, gx2, gy2);
        float lg = pp[l][((size_t)b * CH + 4 * BINSc + lab) * HW + hw];
        float al = align_fn(iou, lg);
        if (al <= EPSf) continue;     // mask-equivalent filter
        if (al > val[9] || (al == val[9] && n < idx[9])) {
            val[9] = al; idx[9] = n;
            #pragma unroll
            for (int k = 9; k >= 1; k--) {
                if (val[k] > val[k - 1] ||
                    (val[k] == val[k - 1] && idx[k] < idx[k - 1])) {
                    float tv = val[k]; val[k] = val[k - 1]; val[k - 1] = tv;
                    int ti = idx[k]; idx[k] = idx[k - 1]; idx[k - 1] = ti;
                }
            }
        }
    }

    // merge across lanes: 10 rounds of u64 argmax (value bits || ~index)
    int cnt = 0;
    for (int it = 0; it < 10; it++) {
        unsigned long long pack =
            ((unsigned long long)(unsigned)__float_as_int(val[0]) << 32) |
            (unsigned)(~(unsigned)idx[0]);
        #pragma unroll
        for (int o = 16; o; o >>= 1) {
            unsigned long long other = __shfl_xor_sync(0xffffffffu, pack, o);
            if (other > pack) pack = other;
        }
        float wv = __int_as_float((int)(pack >> 32));
        if (wv <= EPSf) break;
        int wn = (int)(~(unsigned)pack);
        if (lane == 0) {
            g_topn[row * 10 + it] = wn;
            atomicOr(&g_bits[b * Nn + wn], 1u << g);
        }
        cnt++;
        if (idx[0] == wn) {           // winning lane pops its head
            #pragma unroll
            for (int k = 0; k < 9; k++) { val[k] = val[k + 1]; idx[k] = idx[k + 1]; }
            val[9] = 0.f; idx[9] = 0x7fffffff;
        }
    }
    if (lane == 0) g_topcnt[row] = cnt;
}

// sparse resolve over topn entries + fused row-max atomics
__global__ void k_resolve(const float* __restrict__ p0, const float* __restrict__ p1,
                          const float* __restrict__ p2,
                          const float* __restrict__ gtb, const int* __restrict__ gtl)
{
    int e = blockIdx.x * blockDim.x + threadIdx.x;
    if (e >= Bn * Gn * 10) return;
    int row = e / 10, slot = e % 10;
    if (slot >= g_topcnt[row]) return;
    int b = row / Gn;
    int n = g_topn[row * 10 + slot];
    int t = b * Nn + n;
    if (atomicExch(&g_claim[t], 1)) return;      // already processed
    unsigned int bits = g_bits[t];
    float4 pb = g_pred[t];
    int mg;
    if (__popc(bits) > 1) {
        const float* gbase = gtb + (size_t)b * Gn * 4;
        float bo = -1.f; int bg = 0;
        #pragma unroll 8
        for (int g = 0; g < Gn; g++) {
            float iou = iou_fn(pb, gbase[g * 4 + 0], gbase[g * 4 + 1],
                               gbase[g * 4 + 2], gbase[g * 4 + 3]);
            if (iou > bo) { bo = iou; bg = g; }
        }
        mg = bg;
    } else {
        mg = __ffs(bits) - 1;
    }
    int pos = atomicAdd(&g_cnt, 1);
    g_fglist[pos] = t * 32 + mg;
    const float* gb = gtb + ((size_t)(b * Gn + mg)) * 4;
    float gx1 = gb[0], gy1 = gb[1], gx2 = gb[2], gy2 = gb[3];
    int lab = gtl[b * Gn + mg];
    const float* p; int hw, W, HW; float stride;
    decode_anchor(n, p, p0, p1, p2, hw, W, HW, stride);
    float iou = iou_fn(pb, gx1, gy1, gx2, gy2);
    float l = p[((size_t)b * CH + 4 * BINSc + lab) * HW + hw];
    float al = align_fn(iou, l);
    atomicMax(&g_ovmax_i[b * Gn + mg], __float_as_int(iou));
    atomicMax(&g_almax_i[b * Gn + mg], __float_as_int(al));
}

// per-fg-anchor: norm, CIoU, DFL loss, focal correction; resets claim flags
__global__ void k_anchor(const float* __restrict__ p0, const float* __restrict__ p1,
                         const float* __restrict__ p2,
                         const float* __restrict__ gtb, const int* __restrict__ gtl)
{
    int i = blockIdx.x * blockDim.x + threadIdx.x;   // grid covers MAXFG
    double aciou = 0.0, adfl = 0.0, acorr = 0.0;
    if (i < g_cnt) {
        int code = g_fglist[i];
        int t = code >> 5, mg = code & 31;
        g_claim[t] = 0;                              // self-clean for next run
        int b = t / Nn, n = t % Nn;
        const float* p; int hw, W, HW; float stride;
        decode_anchor(n, p, p0, p1, p2, hw, W, HW, stride);
        float cx = ((hw % W) + 0.5f) * stride;
        float cy = ((hw / W) + 0.5f) * stride;
        const float* gb = gtb + ((size_t)(b * Gn + mg)) * 4;
        float tx1 = gb[0], ty1 = gb[1], tx2 = gb[2], ty2 = gb[3];
        int lab = gtl[b * Gn + mg];
        float4 pb = g_pred[t];
        // ---- norm ----
        float iou0 = iou_fn(pb, tx1, ty1, tx2, ty2);
        float lcls = p[((size_t)b * CH + 4 * BINSc + lab) * HW + hw];
        float al = align_fn(iou0, lcls);
        float ovmax = __int_as_float(g_ovmax_i[b * Gn + mg]);
        float almax = __int_as_float(g_almax_i[b * Gn + mg]);
        float norm = fmaxf(al * ovmax / (almax + EPSf), 0.f);
        // ---- CIoU ----
        float w1 = pb.z - pb.x, h1 = pb.w - pb.y;
        float w2 = tx2 - tx1,   h2 = ty2 - ty1;
        float iw = fmaxf(fminf(pb.z, tx2) - fmaxf(pb.x, tx1), 0.f);
        float ih = fmaxf(fminf(pb.w, ty2) - fmaxf(pb.y, ty1), 0.f);
        float inter = iw * ih;
        float uni = w1 * h1 + w2 * h2 - inter + EPSf;
        float iou = inter / uni;
        float cw  = fmaxf(pb.z, tx2) - fminf(pb.x, tx1);
        float chh = fmaxf(pb.w, ty2) - fminf(pb.y, ty1);
        float c2  = cw * cw + chh * chh + EPSf;
        float dx = pb.x + pb.z - tx1 - tx2;
        float dy = pb.y + pb.w - ty1 - ty2;
        float rho2 = (dx * dx + dy * dy) * 0.25f;
        float dat = atanf(w2 / (h2 + EPSf)) - atanf(w1 / (h1 + EPSf));
        float v = (4.f / (float)(CUDART_PI * CUDART_PI)) * dat * dat;
        float alpha = v / (v - iou + 1.f + EPSf);
        aciou = (double)(1.f - (iou - rho2 / c2 - v * alpha));
        // ---- DFL ----
        const float* base = p + ((size_t)b * CH) * HW + hw;
        float4 lse4 = g_lse[t];
        float lsea[4] = { lse4.x, lse4.y, lse4.z, lse4.w };
        float dd[4] = { fmaxf(cx - tx1, 0.f), fmaxf(cy - ty1, 0.f),
                        fmaxf(tx2 - cx, 0.f), fmaxf(ty2 - cy, 0.f) };
        float sdfl = 0.f;
        #pragma unroll
        for (int s = 0; s < 4; s++) {
            float d = fminf(fmaxf(dd[s] / stride, 0.f), (float)(BINSc - 1) - 1e-6f);
            float lo = floorf(d);
            float a  = d - lo;
            int li = (int)lo;
            float llo = base[(size_t)(s * BINSc + li) * HW];
            float lup = base[(size_t)(s * BINSc + li + 1) * HW];
            sdfl -= (1.f - a) * (llo - lsea[s]) + a * (lup - lsea[s]);
        }
        adfl = (double)sdfl;
        // ---- focal correction at matched label ----
        float l = lcls;
        float pr = 1.f / (1.f + expf(-l));
        float b0 = focal_base(l);
        float tt = norm;
        float ce = fmaxf(l, 0.f) - l * tt + log1pf(expf(-fabsf(l)));
        float pt = pr * tt + (1.f - pr) * (1.f - tt);
        float at = 0.25f * tt + 0.75f * (1.f - tt);
        acorr = (double)(at * (1.f - pt) * (1.f - pt) * ce - b0);
    }
    double r;
    r = blkReduce(aciou); if (threadIdx.x == 0 && r != 0.0) atomicAdd(&g_acc[0], r);
    r = blkReduce(adfl);  if (threadIdx.x == 0 && r != 0.0) atomicAdd(&g_acc[1], r);
    r = blkReduce(acorr); if (threadIdx.x == 0 && r != 0.0) atomicAdd(&g_acc[2], r);
}

// write outputs, then reset all accumulators/maxima for the next replay
__global__ void k_final(float* out)
{
    int t = threadIdx.x;
    if (t == 0) {
        double den = (double)(g_cnt > 1 ? g_cnt : 1);
        out[0] = (float)(7.5 * g_acc[0] / den);
        out[1] = (float)(1.5 * g_acc[1] / den);
        out[2] = (float)(0.5 * g_acc[2] / den);
        g_acc[0] = 0.0; g_acc[1] = 0.0; g_acc[2] = 0.0;
        g_cnt = 0;
    }
    if (t < Bn * Gn) { g_ovmax_i[t] = 0; g_almax_i[t] = 0; }
}

// ---------------- launch ----------------
extern "C" void kernel_launch(void* const* d_in, const int* in_sizes, int n_in,
                              void* d_out, int out_size)
{
    const float* p0  = (const float*)d_in[0];
    const float* p1  = (const float*)d_in[1];
    const float* p2  = (const float*)d_in[2];
    const float* gtb = (const float*)d_in[3];
    const int*   gtl = (const int*)d_in[4];
    float* out = (float*)d_out;

    k_pred<<<(Bn * Nn) / 256, 256>>>(p0, p1, p2);          // 525 blocks, exact
    k_pairtopk<<<(Bn * Gn * 32) / 128, 128>>>(p0, p1, p2, gtb, gtl); // 1 warp/row
    k_resolve<<<MAXFG / 256, 256>>>(p0, p1, p2, gtb, gtl);
    k_anchor<<<MAXFG / 256, 256>>>(p0, p1, p2, gtb, gtl);
    k_final<<<1, 512>>>(out);
}